// round 7
// baseline (speedup 1.0000x reference)
#include <cuda_runtime.h>
#include <cstdint>

#define BDIM 256
#define TDIM 1024
#define U    32
#define UNF  6
#define EPSV 1e-8f
#define AMAX 18
#define SMAX 32
#define FULLM 0xffffffffu
#define NTICK (TDIM * (BDIM / 8))   // 32768 tickets, 8 batch-rows each
#define NSCANBLK 128

// 64 MB scratch: precomputed sensory (num, den) per (b,t,unit)
__device__ float2 g_sens[(size_t)BDIM * TDIM * U];
// per-timestep completion counters (32 tickets per t)
__device__ int g_cnt[TDIM];

// per-column sparse recurrent lists (tanh form), layout [k*U + col]
__device__ int   g_asrc[AMAX * U];
__device__ float g_aa[AMAX * U], g_ab[AMAX * U], g_aweh[AMAX * U], g_awdh[AMAX * U];
__device__ float g_anum0[U], g_aden0[U];
__device__ int   g_na;

// per-column sparse sensory lists (tanh form)
__device__ int   g_ssrc[SMAX * U];
__device__ float g_sa[SMAX * U], g_sb[SMAX * U], g_sweh[SMAX * U], g_swdh[SMAX * U];
__device__ float g_snum0[U], g_sden0[U];
__device__ int   g_ns;

__device__ __forceinline__ float tanhf_a(float x) {
    float r; asm("tanh.approx.f32 %0, %1;" : "=f"(r) : "f"(x)); return r;
}
__device__ __forceinline__ float rcpf(float x) {
    float r; asm("rcp.approx.ftz.f32 %0, %1;" : "=f"(r) : "f"(x)); return r;
}
__device__ __forceinline__ int ld_acq(const int* p) {
    int v; asm volatile("ld.acquire.gpu.global.b32 %0, [%1];" : "=r"(v) : "l"(p)); return v;
}

// ---------------------------------------------------------------------------
// Setup (R4 version): per-column lists, tanh form.
// sigmoid(s(v-mu)) = 0.5 + 0.5*tanh(a*v - b), a = 0.5*s, b = 0.5*s*mu.
// ---------------------------------------------------------------------------
__global__ void __launch_bounds__(1024) setup_kernel(
    const int* __restrict__ spm, const float* __restrict__ wsyn,
    const float* __restrict__ mu, const float* __restrict__ sg,
    const float* __restrict__ er,
    const int* __restrict__ ssm, const float* __restrict__ sw,
    const float* __restrict__ smu, const float* __restrict__ ssg,
    const float* __restrict__ ser)
{
    __shared__ int   s_m[1024]; __shared__ float s_w[1024], s_mu[1024], s_sg[1024], s_er[1024];
    __shared__ int   t_m[1024]; __shared__ float t_w[1024], t_mu[1024], t_sg[1024], t_er[1024];
    int tid = threadIdx.x;
    g_cnt[tid] = 0;                            // reset readiness counters (every launch)
    s_m[tid] = spm[tid]; s_w[tid] = wsyn[tid]; s_mu[tid] = mu[tid];
    s_sg[tid] = sg[tid]; s_er[tid] = er[tid];
    t_m[tid] = ssm[tid]; t_w[tid] = sw[tid];  t_mu[tid] = smu[tid];
    t_sg[tid] = ssg[tid]; t_er[tid] = ser[tid];
    __syncthreads();

    if (tid < 32) {                       // recurrent lists, column j = tid
        int j = tid, cnt = 0;
        float n0 = 0.f, d0 = 0.f;
        for (int i = 0; i < U; i++) {
            int idx = i * U + j;
            if (s_m[idx] != 0 && cnt < AMAX) {
                float a = 0.5f * s_sg[idx];
                float weh = 0.5f * s_w[idx] * s_er[idx];
                float wdh = 0.5f * s_w[idx];
                g_asrc[cnt * U + j] = i;
                g_aa[cnt * U + j]   = a;
                g_ab[cnt * U + j]   = a * s_mu[idx];
                g_aweh[cnt * U + j] = weh;
                g_awdh[cnt * U + j] = wdh;
                n0 += weh; d0 += wdh;
                cnt++;
            }
        }
        for (int k = cnt; k < AMAX; k++) {
            g_asrc[k * U + j] = 0;
            g_aa[k * U + j] = 0.f; g_ab[k * U + j] = 0.f;
            g_aweh[k * U + j] = 0.f; g_awdh[k * U + j] = 0.f;
        }
        g_anum0[j] = n0; g_aden0[j] = d0;
        int m = cnt;
        #pragma unroll
        for (int o = 16; o > 0; o >>= 1) m = max(m, __shfl_xor_sync(FULLM, m, o));
        if (j == 0) g_na = m;
    } else if (tid < 64) {                // sensory lists, column j = tid-32
        int j = tid - 32, cnt = 0;
        float n0 = 0.f, d0 = 0.f;
        for (int i = 0; i < U; i++) {
            int idx = i * U + j;
            if (t_m[idx] != 0 && cnt < SMAX) {
                float a = 0.5f * t_sg[idx];
                float weh = 0.5f * t_w[idx] * t_er[idx];
                float wdh = 0.5f * t_w[idx];
                g_ssrc[cnt * U + j] = i;
                g_sa[cnt * U + j]   = a;
                g_sb[cnt * U + j]   = a * t_mu[idx];
                g_sweh[cnt * U + j] = weh;
                g_swdh[cnt * U + j] = wdh;
                n0 += weh; d0 += wdh;
                cnt++;
            }
        }
        for (int k = cnt; k < SMAX; k++) {
            g_ssrc[k * U + j] = 0;
            g_sa[k * U + j] = 0.f; g_sb[k * U + j] = 0.f;
            g_sweh[k * U + j] = 0.f; g_swdh[k * U + j] = 0.f;
        }
        g_snum0[j] = n0; g_sden0[j] = d0;
        int m = cnt;
        #pragma unroll
        for (int o = 16; o > 0; o >>= 1) m = max(m, __shfl_xor_sync(FULLM, m, o));
        if (j == 0) g_ns = m;
    }
}

// ---------------------------------------------------------------------------
// Fused kernel, HARD ROLE SEPARATION:
//   blocks 0..127   : warps 0,1 = scan (batches 2*bid, 2*bid+1); warps 2-7 EXIT.
//                     No sens warps -> no LDS traffic competing with scan shfls
//                     on the per-SM MIO unit.
//   blocks 128..end : 8 sens warps each (20 SMs worth of producers).
// ---------------------------------------------------------------------------
__device__ void sens_warp(
    int sw, int nw, int warp, int lane, float* smem,
    const float* __restrict__ x,
    const float* __restrict__ d1w, const float* __restrict__ d1b,
    const float* __restrict__ d2b,
    const float* __restrict__ iw,  const float* __restrict__ ib)
{
    float* sh_w2t = smem;                       // [32][132]
    float* sh_h1  = smem + 32 * 132 + warp * 1024;            // [8][128] per warp
    float* sh_in  = smem + 32 * 132 + 8 * 1024 + warp * 256;  // [8][32] per warp

    float wa[4], wb[4], bb[4];
    #pragma unroll
    for (int c = 0; c < 4; c++) {
        int k = c * 32 + lane;
        wa[c] = d1w[k]; wb[c] = d1w[128 + k]; bb[c] = d1b[k];
    }
    float dbl = d2b[lane], iwl = iw[lane], ibl = ib[lane];
    float n0 = g_snum0[lane], d0 = g_sden0[lane];
    int ns = g_ns;

    for (int q = sw; q < NTICK; q += nw) {
        int t  = q >> 5;
        int b0 = (q & 31) << 3;

        float2 xv = make_float2(0.f, 0.f);
        if (lane < 8) xv = ((const float2*)x)[(size_t)(b0 + lane) * TDIM + t];

        #pragma unroll
        for (int r = 0; r < 8; r++) {
            float x0 = __shfl_sync(FULLM, xv.x, r);
            float x1 = __shfl_sync(FULLM, xv.y, r);
            #pragma unroll
            for (int c = 0; c < 4; c++) {
                int k = c * 32 + lane;
                sh_h1[r * 128 + k] = fmaxf(fmaf(x0, wa[c], fmaf(x1, wb[c], bb[c])), 0.f);
            }
        }
        __syncwarp();

        float acc[8];
        #pragma unroll
        for (int r = 0; r < 8; r++) acc[r] = dbl;
        #pragma unroll 8
        for (int kq = 0; kq < 32; kq++) {
            float4 w4 = *(const float4*)&sh_w2t[lane * 132 + kq * 4];
            #pragma unroll
            for (int r = 0; r < 8; r++) {
                float4 h4 = *(const float4*)&sh_h1[r * 128 + kq * 4];
                acc[r] = fmaf(h4.x, w4.x, acc[r]);
                acc[r] = fmaf(h4.y, w4.y, acc[r]);
                acc[r] = fmaf(h4.z, w4.z, acc[r]);
                acc[r] = fmaf(h4.w, w4.w, acc[r]);
            }
        }
        #pragma unroll
        for (int r = 0; r < 8; r++) sh_in[r * 32 + lane] = fmaf(acc[r], iwl, ibl);
        __syncwarp();

        float num[8], den[8];
        #pragma unroll
        for (int r = 0; r < 8; r++) { num[r] = n0; den[r] = d0; }
        for (int k = 0; k < ns; k++) {
            int   src = g_ssrc[k * U + lane];
            float a   = g_sa[k * U + lane];
            float b   = g_sb[k * U + lane];
            float weh = g_sweh[k * U + lane];
            float wdh = g_swdh[k * U + lane];
            #pragma unroll
            for (int r = 0; r < 8; r++) {
                float tk = tanhf_a(fmaf(a, sh_in[r * 32 + src], -b));
                num[r] = fmaf(weh, tk, num[r]);
                den[r] = fmaf(wdh, tk, den[r]);
            }
        }
        #pragma unroll
        for (int r = 0; r < 8; r++)
            g_sens[((size_t)(b0 + r) * TDIM + t) * U + lane] = make_float2(num[r], den[r]);

        __threadfence();                        // release: data before counter
        if (lane == 0) atomicAdd(&g_cnt[t], 1);
        __syncwarp();
    }
}

__device__ __forceinline__ void verify16(int base) {
    for (;;) {
        int ok = 1;
        #pragma unroll
        for (int i = 0; i < 16; i++)
            ok &= (ld_acq(&g_cnt[base + i]) == 32);
        if (ok) return;
        __nanosleep(200);
    }
}

// R4 scan body (best measured): NA shfl+tanh per lane, 4-way fma chains.
template <int NA>
__device__ void scan_body(
    int lane, int batch,
    const float* __restrict__ gleak, const float* __restrict__ vleak,
    const float* __restrict__ cm,
    const float* __restrict__ ow, const float* __restrict__ ob,
    float* __restrict__ out)
{
    float gl   = gleak[lane];
    float cmt  = cm[lane] * (float)UNF;
    float gv   = gl * vleak[lane];
    float dcst = cmt + gl + EPSV + g_aden0[lane];
    float ncst = g_anum0[lane];

    int src[NA]; float a[NA], b[NA], weh[NA], wdh[NA];
    #pragma unroll
    for (int k = 0; k < NA; k++) {
        src[k] = g_asrc[k * U + lane];
        a[k]   = g_aa[k * U + lane];
        b[k]   = g_ab[k * U + lane];
        weh[k] = g_aweh[k * U + lane];
        wdh[k] = g_awdh[k * U + lane];
    }

    const float2* sp = g_sens + (size_t)batch * TDIM * U + lane;

    verify16(0);
    float2 sv = sp[0];
    float v = 0.f;

    for (int t = 0; t < TDIM; t++) {
        if ((t & 15) == 0 && t + 16 < TDIM) verify16(t + 16);  // stay 16 steps ahead
        int tn = (t + 1 < TDIM) ? (t + 1) : t;
        float2 nxt = sp[(size_t)tn * U];

        float nb = sv.x + ncst + gv;
        float db = sv.y + dcst;

        #pragma unroll
        for (int u = 0; u < UNF; u++) {
            float tk[NA];
            #pragma unroll
            for (int k = 0; k < NA; k++) {
                float vs = __shfl_sync(FULLM, v, src[k]);
                tk[k] = tanhf_a(fmaf(a[k], vs, -b[k]));
            }
            // den chains first -> rcp overlaps num chains
            float dch[4];
            dch[0] = db; dch[1] = 0.f; dch[2] = 0.f; dch[3] = 0.f;
            #pragma unroll
            for (int k = 0; k < NA; k++)
                dch[k & 3] = fmaf(wdh[k], tk[k], dch[k & 3]);
            float den  = (dch[0] + dch[1]) + (dch[2] + dch[3]);
            float rden = rcpf(den);

            float nch[4];
            nch[0] = fmaf(cmt, v, nb); nch[1] = 0.f; nch[2] = 0.f; nch[3] = 0.f;
            #pragma unroll
            for (int k = 0; k < NA; k++)
                nch[k & 3] = fmaf(weh[k], tk[k], nch[k & 3]);
            float num = (nch[0] + nch[1]) + (nch[2] + nch[3]);

            v = num * rden;
        }
        sv = nxt;
    }

    if (lane == 0) out[batch] = fmaf(v, ow[0], ob[0]);
}

__global__ void __launch_bounds__(256) fused_kernel(
    const float* __restrict__ x,
    const float* __restrict__ d1w, const float* __restrict__ d1b,
    const float* __restrict__ d2w, const float* __restrict__ d2b,
    const float* __restrict__ iw,  const float* __restrict__ ib,
    const float* __restrict__ gleak, const float* __restrict__ vleak,
    const float* __restrict__ cm,
    const float* __restrict__ ow, const float* __restrict__ ob,
    float* __restrict__ out)
{
    extern __shared__ float smem[];
    int tid = threadIdx.x, warp = tid >> 5, lane = tid & 31;

    if (blockIdx.x < NSCANBLK) {
        // scan-only block: no smem staging, no sens warps, no MIO contention
        if (warp >= 2) return;
        int batch = blockIdx.x * 2 + warp;
        int na = g_na;
        if      (na <= 4)  scan_body<4 >(lane, batch, gleak, vleak, cm, ow, ob, out);
        else if (na <= 6)  scan_body<6 >(lane, batch, gleak, vleak, cm, ow, ob, out);
        else if (na <= 8)  scan_body<8 >(lane, batch, gleak, vleak, cm, ow, ob, out);
        else if (na <= 10) scan_body<10>(lane, batch, gleak, vleak, cm, ow, ob, out);
        else if (na <= 12) scan_body<12>(lane, batch, gleak, vleak, cm, ow, ob, out);
        else               scan_body<18>(lane, batch, gleak, vleak, cm, ow, ob, out);
    } else {
        // sens block: stage d2_w transposed [j][k] padded to 132, then produce
        for (int i = tid; i < 128 * 32; i += 256) {
            int k = i >> 5, j = i & 31;
            smem[j * 132 + k] = d2w[i];
        }
        __syncthreads();
        int sw = (blockIdx.x - NSCANBLK) * 8 + warp;
        int nw = (gridDim.x - NSCANBLK) * 8;
        sens_warp(sw, nw, warp, lane, smem, x, d1w, d1b, d2b, iw, ib);
    }
}

// ---------------------------------------------------------------------------
extern "C" void kernel_launch(void* const* d_in, const int* in_sizes, int n_in,
                              void* d_out, int out_size)
{
    const float* x    = (const float*)d_in[0];
    const float* d1w  = (const float*)d_in[1];
    const float* d1b  = (const float*)d_in[2];
    const float* d2w  = (const float*)d_in[3];
    const float* d2b  = (const float*)d_in[4];
    const float* iw   = (const float*)d_in[5];
    const float* ib   = (const float*)d_in[6];
    const float* ow   = (const float*)d_in[7];
    const float* ob   = (const float*)d_in[8];
    const float* gle  = (const float*)d_in[9];
    const float* vle  = (const float*)d_in[10];
    const float* cmv  = (const float*)d_in[11];
    const float* wsyn = (const float*)d_in[12];
    const float* muv  = (const float*)d_in[13];
    const float* sgv  = (const float*)d_in[14];
    const float* erv  = (const float*)d_in[15];
    const float* swv  = (const float*)d_in[16];
    const float* smuv = (const float*)d_in[17];
    const float* ssgv = (const float*)d_in[18];
    const float* serv = (const float*)d_in[19];
    const int*   spm  = (const int*)d_in[20];
    const int*   ssm  = (const int*)d_in[21];

    int nsm = 148;
    cudaDeviceGetAttribute(&nsm, cudaDevAttrMultiProcessorCount, 0);
    int blocks = (nsm > NSCANBLK) ? nsm : (NSCANBLK + 1);  // >=1 sens block

    const int smemBytes = (32 * 132 + 8 * 1024 + 8 * 256) * sizeof(float);
    cudaFuncSetAttribute(fused_kernel, cudaFuncAttributeMaxDynamicSharedMemorySize, smemBytes);

    setup_kernel<<<1, 1024>>>(spm, wsyn, muv, sgv, erv, ssm, swv, smuv, ssgv, serv);
    fused_kernel<<<blocks, 256, smemBytes>>>(x, d1w, d1b, d2w, d2b, iw, ib,
                                             gle, vle, cmv, ow, ob, (float*)d_out);
}

// round 8
// speedup vs baseline: 1.4164x; 1.4164x over previous
#include <cuda_runtime.h>
#include <cstdint>

#define BDIM 256
#define TDIM 1024
#define U    32
#define UNF  6
#define EPSV 1e-8f
#define AMAX 18
#define SMAX 32
#define NLOCMAX 10
#define NXMAX 8
#define FULLM 0xffffffffu
#define NTICK (TDIM * (BDIM / 8))   // 32768 tickets, 8 batch-rows each

// 64 MB scratch: precomputed sensory (num, den) per (b,t,unit)
__device__ float2 g_sens[(size_t)BDIM * TDIM * U];
__device__ int g_cnt[TDIM];

// classic per-column recurrent lists (tanh form) — also the fallback scan path
__device__ int   g_asrc[AMAX * U];
__device__ float g_aa[AMAX * U], g_ab[AMAX * U], g_aweh[AMAX * U], g_awdh[AMAX * U];
__device__ float g_anum0[U], g_aden0[U];
__device__ int   g_na;

// split lists: local edges (src has recurrent in-degree 0) vs cross edges
__device__ int   g_lsrc[NLOCMAX * U];
__device__ float g_la[NLOCMAX * U], g_lb[NLOCMAX * U], g_lwe[NLOCMAX * U], g_lwd[NLOCMAX * U];
__device__ int   g_xsrc[NXMAX * U];
__device__ float g_xa[NXMAX * U], g_xb[NXMAX * U], g_xwe[NXMAX * U], g_xwd[NXMAX * U];
__device__ int   g_nloc, g_ncross, g_splitok;

// per-column sparse sensory lists (tanh form)
__device__ int   g_ssrc[SMAX * U];
__device__ float g_sa[SMAX * U], g_sb[SMAX * U], g_sweh[SMAX * U], g_swdh[SMAX * U];
__device__ float g_snum0[U], g_sden0[U];
__device__ int   g_ns;

__device__ __forceinline__ float tanhf_a(float x) {
    float r; asm("tanh.approx.f32 %0, %1;" : "=f"(r) : "f"(x)); return r;
}
__device__ __forceinline__ float rcpf(float x) {
    float r; asm("rcp.approx.ftz.f32 %0, %1;" : "=f"(r) : "f"(x)); return r;
}
__device__ __forceinline__ int ld_acq(const int* p) {
    int v; asm volatile("ld.acquire.gpu.global.b32 %0, [%1];" : "=r"(v) : "l"(p)); return v;
}

// ---------------------------------------------------------------------------
// Setup: classic lists (tid<32), sensory lists (tid 32..63), split lists (tid 64).
// sigmoid(s(v-mu)) = 0.5 + 0.5*tanh(a*v - b); constant halves fold into num0/den0.
// ---------------------------------------------------------------------------
__global__ void __launch_bounds__(1024) setup_kernel(
    const int* __restrict__ spm, const float* __restrict__ wsyn,
    const float* __restrict__ mu, const float* __restrict__ sg,
    const float* __restrict__ er,
    const int* __restrict__ ssm, const float* __restrict__ sw,
    const float* __restrict__ smu, const float* __restrict__ ssg,
    const float* __restrict__ ser)
{
    __shared__ int   s_m[1024]; __shared__ float s_w[1024], s_mu[1024], s_sg[1024], s_er[1024];
    __shared__ int   t_m[1024]; __shared__ float t_w[1024], t_mu[1024], t_sg[1024], t_er[1024];
    int tid = threadIdx.x;
    g_cnt[tid] = 0;
    s_m[tid] = spm[tid]; s_w[tid] = wsyn[tid]; s_mu[tid] = mu[tid];
    s_sg[tid] = sg[tid]; s_er[tid] = er[tid];
    t_m[tid] = ssm[tid]; t_w[tid] = sw[tid];  t_mu[tid] = smu[tid];
    t_sg[tid] = ssg[tid]; t_er[tid] = ser[tid];
    __syncthreads();

    if (tid < 32) {                       // classic recurrent lists, column j = tid
        int j = tid, cnt = 0;
        float n0 = 0.f, d0 = 0.f;
        for (int i = 0; i < U; i++) {
            int idx = i * U + j;
            if (s_m[idx] != 0 && cnt < AMAX) {
                float a = 0.5f * s_sg[idx];
                float weh = 0.5f * s_w[idx] * s_er[idx];
                float wdh = 0.5f * s_w[idx];
                g_asrc[cnt * U + j] = i;
                g_aa[cnt * U + j]   = a;
                g_ab[cnt * U + j]   = a * s_mu[idx];
                g_aweh[cnt * U + j] = weh;
                g_awdh[cnt * U + j] = wdh;
                n0 += weh; d0 += wdh;
                cnt++;
            }
        }
        for (int k = cnt; k < AMAX; k++) {
            g_asrc[k * U + j] = 0;
            g_aa[k * U + j] = 0.f; g_ab[k * U + j] = 0.f;
            g_aweh[k * U + j] = 0.f; g_awdh[k * U + j] = 0.f;
        }
        g_anum0[j] = n0; g_aden0[j] = d0;
        int m = cnt;
        #pragma unroll
        for (int o = 16; o > 0; o >>= 1) m = max(m, __shfl_xor_sync(FULLM, m, o));
        if (j == 0) g_na = m;
    } else if (tid < 64) {                // sensory lists, column j = tid-32
        int j = tid - 32, cnt = 0;
        float n0 = 0.f, d0 = 0.f;
        for (int i = 0; i < U; i++) {
            int idx = i * U + j;
            if (t_m[idx] != 0 && cnt < SMAX) {
                float a = 0.5f * t_sg[idx];
                float weh = 0.5f * t_w[idx] * t_er[idx];
                float wdh = 0.5f * t_w[idx];
                g_ssrc[cnt * U + j] = i;
                g_sa[cnt * U + j]   = a;
                g_sb[cnt * U + j]   = a * t_mu[idx];
                g_sweh[cnt * U + j] = weh;
                g_swdh[cnt * U + j] = wdh;
                n0 += weh; d0 += wdh;
                cnt++;
            }
        }
        for (int k = cnt; k < SMAX; k++) {
            g_ssrc[k * U + j] = 0;
            g_sa[k * U + j] = 0.f; g_sb[k * U + j] = 0.f;
            g_sweh[k * U + j] = 0.f; g_swdh[k * U + j] = 0.f;
        }
        g_snum0[j] = n0; g_sden0[j] = d0;
        int m = cnt;
        #pragma unroll
        for (int o = 16; o > 0; o >>= 1) m = max(m, __shfl_xor_sync(FULLM, m, o));
        if (j == 0) g_ns = m;
    } else if (tid == 64) {               // split local/cross lists (single thread)
        int indeg[U];
        for (int j = 0; j < U; j++) {
            int d = 0;
            for (int i = 0; i < U; i++) if (s_m[i * U + j] != 0) d++;
            indeg[j] = d;
        }
        int mnl = 0, mnx = 0, ok = 1;
        for (int j = 0; j < U; j++) {
            int nl = 0, nx = 0;
            for (int i = 0; i < U; i++) {
                int idx = i * U + j;
                if (s_m[idx] == 0) continue;
                float a   = 0.5f * s_sg[idx];
                float b   = a * s_mu[idx];
                float weh = 0.5f * s_w[idx] * s_er[idx];
                float wdh = 0.5f * s_w[idx];
                if (indeg[i] == 0 && nl < NLOCMAX) {
                    g_lsrc[nl * U + j] = i;
                    g_la[nl * U + j] = a;  g_lb[nl * U + j] = b;
                    g_lwe[nl * U + j] = weh; g_lwd[nl * U + j] = wdh;
                    nl++;
                } else if (nx < NXMAX) {
                    g_xsrc[nx * U + j] = i;
                    g_xa[nx * U + j] = a;  g_xb[nx * U + j] = b;
                    g_xwe[nx * U + j] = weh; g_xwd[nx * U + j] = wdh;
                    nx++;
                } else ok = 0;
            }
            for (int k = nl; k < NLOCMAX; k++) {
                g_lsrc[k * U + j] = 0;
                g_la[k * U + j] = 0.f; g_lb[k * U + j] = 0.f;
                g_lwe[k * U + j] = 0.f; g_lwd[k * U + j] = 0.f;
            }
            for (int k = nx; k < NXMAX; k++) {
                g_xsrc[k * U + j] = 0;
                g_xa[k * U + j] = 0.f; g_xb[k * U + j] = 0.f;
                g_xwe[k * U + j] = 0.f; g_xwd[k * U + j] = 0.f;
            }
            if (nl > mnl) mnl = nl;
            if (nx > mnx) mnx = nx;
        }
        g_nloc = mnl; g_ncross = mnx; g_splitok = ok;
    }
}

// ---------------------------------------------------------------------------
// sens worker (verbatim from the 655us R4 version)
// ---------------------------------------------------------------------------
__device__ void sens_warp(
    int sw, int nw, int warp, int lane, float* smem,
    const float* __restrict__ x,
    const float* __restrict__ d1w, const float* __restrict__ d1b,
    const float* __restrict__ d2b,
    const float* __restrict__ iw,  const float* __restrict__ ib)
{
    float* sh_w2t = smem;
    float* sh_h1  = smem + 32 * 132 + warp * 1024;
    float* sh_in  = smem + 32 * 132 + 8 * 1024 + warp * 256;

    float wa[4], wb[4], bb[4];
    #pragma unroll
    for (int c = 0; c < 4; c++) {
        int k = c * 32 + lane;
        wa[c] = d1w[k]; wb[c] = d1w[128 + k]; bb[c] = d1b[k];
    }
    float dbl = d2b[lane], iwl = iw[lane], ibl = ib[lane];
    float n0 = g_snum0[lane], d0 = g_sden0[lane];
    int ns = g_ns;

    for (int q = sw; q < NTICK; q += nw) {
        int t  = q >> 5;
        int b0 = (q & 31) << 3;

        float2 xv = make_float2(0.f, 0.f);
        if (lane < 8) xv = ((const float2*)x)[(size_t)(b0 + lane) * TDIM + t];

        #pragma unroll
        for (int r = 0; r < 8; r++) {
            float x0 = __shfl_sync(FULLM, xv.x, r);
            float x1 = __shfl_sync(FULLM, xv.y, r);
            #pragma unroll
            for (int c = 0; c < 4; c++) {
                int k = c * 32 + lane;
                sh_h1[r * 128 + k] = fmaxf(fmaf(x0, wa[c], fmaf(x1, wb[c], bb[c])), 0.f);
            }
        }
        __syncwarp();

        float acc[8];
        #pragma unroll
        for (int r = 0; r < 8; r++) acc[r] = dbl;
        #pragma unroll 8
        for (int kq = 0; kq < 32; kq++) {
            float4 w4 = *(const float4*)&sh_w2t[lane * 132 + kq * 4];
            #pragma unroll
            for (int r = 0; r < 8; r++) {
                float4 h4 = *(const float4*)&sh_h1[r * 128 + kq * 4];
                acc[r] = fmaf(h4.x, w4.x, acc[r]);
                acc[r] = fmaf(h4.y, w4.y, acc[r]);
                acc[r] = fmaf(h4.z, w4.z, acc[r]);
                acc[r] = fmaf(h4.w, w4.w, acc[r]);
            }
        }
        #pragma unroll
        for (int r = 0; r < 8; r++) sh_in[r * 32 + lane] = fmaf(acc[r], iwl, ibl);
        __syncwarp();

        float num[8], den[8];
        #pragma unroll
        for (int r = 0; r < 8; r++) { num[r] = n0; den[r] = d0; }
        for (int k = 0; k < ns; k++) {
            int   src = g_ssrc[k * U + lane];
            float a   = g_sa[k * U + lane];
            float b   = g_sb[k * U + lane];
            float weh = g_sweh[k * U + lane];
            float wdh = g_swdh[k * U + lane];
            #pragma unroll
            for (int r = 0; r < 8; r++) {
                float tk = tanhf_a(fmaf(a, sh_in[r * 32 + src], -b));
                num[r] = fmaf(weh, tk, num[r]);
                den[r] = fmaf(wdh, tk, den[r]);
            }
        }
        #pragma unroll
        for (int r = 0; r < 8; r++)
            g_sens[((size_t)(b0 + r) * TDIM + t) * U + lane] = make_float2(num[r], den[r]);

        __threadfence();
        if (lane == 0) atomicAdd(&g_cnt[t], 1);
        __syncwarp();
    }
}

__device__ __forceinline__ void verify8(int base) {
    for (;;) {
        int ok = 1;
        #pragma unroll
        for (int i = 0; i < 8; i++)
            ok &= (ld_acq(&g_cnt[base + i]) == 32);
        if (ok) return;
        __nanosleep(200);
    }
}

// ---------------------------------------------------------------------------
// Split scan: NL local edges (replicated deg-0 source states, no shfl wait)
// + NX cross edges (shfl wave). Local tanhs issue from cycle 0 of each unfold.
// ---------------------------------------------------------------------------
template <int NL, int NX>
__device__ void scan_split(
    int lane, int batch,
    const float* __restrict__ gleak, const float* __restrict__ vleak,
    const float* __restrict__ cm,
    const float* __restrict__ ow, const float* __restrict__ ob,
    float* __restrict__ out)
{
    float gl   = gleak[lane];
    float cmt  = cm[lane] * (float)UNF;
    float gv   = gl * vleak[lane];
    float dcst = cmt + gl + EPSV + g_aden0[lane];
    float ncst = g_anum0[lane];
    float myden0 = cmt + gl + EPSV;     // deg-0 unit: constant denominator base

    int   lsrc[NL]; float la[NL], lb[NL], lwe[NL], lwd[NL];
    float lcmt[NL], lgv[NL], lden0[NL], lv[NL], lk[NL], lr[NL];
    #pragma unroll
    for (int e = 0; e < NL; e++) {
        lsrc[e] = g_lsrc[e * U + lane];
        la[e]   = g_la[e * U + lane];
        lb[e]   = g_lb[e * U + lane];
        lwe[e]  = g_lwe[e * U + lane];
        lwd[e]  = g_lwd[e * U + lane];
        lv[e]   = 0.f;
    }
    #pragma unroll
    for (int e = 0; e < NL; e++) {
        lcmt[e]  = __shfl_sync(FULLM, cmt, lsrc[e]);
        lgv[e]   = __shfl_sync(FULLM, gv, lsrc[e]);
        lden0[e] = __shfl_sync(FULLM, myden0, lsrc[e]);
    }

    int xsrc[NX]; float xa[NX], xb[NX], xwe[NX], xwd[NX];
    #pragma unroll
    for (int c = 0; c < NX; c++) {
        xsrc[c] = g_xsrc[c * U + lane];
        xa[c]   = g_xa[c * U + lane];
        xb[c]   = g_xb[c * U + lane];
        xwe[c]  = g_xwe[c * U + lane];
        xwd[c]  = g_xwd[c * U + lane];
    }

    const float2* sp = g_sens + (size_t)batch * TDIM * U + lane;

    verify8(0);
    float2 sv = sp[0];
    float v = 0.f;

    for (int t = 0; t < TDIM; t++) {
        if ((t & 7) == 0 && t + 8 < TDIM) verify8(t + 8);
        int tn = (t + 1 < TDIM) ? (t + 1) : t;
        float2 nxt = sp[(size_t)tn * U];

        float nb = sv.x + ncst + gv;
        float db = sv.y + dcst;

        // per-timestep constants for replicated deg-0 sources (off critical chain)
        #pragma unroll
        for (int e = 0; e < NL; e++) {
            float sx = __shfl_sync(FULLM, sv.x, lsrc[e]);
            float sy = __shfl_sync(FULLM, sv.y, lsrc[e]);
            lk[e] = lgv[e] + sx;
            lr[e] = rcpf(sy + lden0[e]);
        }

        #pragma unroll
        for (int u = 0; u < UNF; u++) {
            // cross shfls (latency overlapped by local tanh issue)
            float vs[NX];
            #pragma unroll
            for (int c = 0; c < NX; c++) vs[c] = __shfl_sync(FULLM, v, xsrc[c]);
            // local tanhs: args ready at cycle 0
            float lt[NL];
            #pragma unroll
            for (int e = 0; e < NL; e++) lt[e] = tanhf_a(fmaf(la[e], lv[e], -lb[e]));
            float xt[NX];
            #pragma unroll
            for (int c = 0; c < NX; c++) xt[c] = tanhf_a(fmaf(xa[c], vs[c], -xb[c]));

            // den chains first -> rcp overlaps num chains
            float dch[4];
            dch[0] = db; dch[1] = 0.f; dch[2] = 0.f; dch[3] = 0.f;
            #pragma unroll
            for (int e = 0; e < NL; e++) dch[e & 3] = fmaf(lwd[e], lt[e], dch[e & 3]);
            #pragma unroll
            for (int c = 0; c < NX; c++) dch[(NL + c) & 3] = fmaf(xwd[c], xt[c], dch[(NL + c) & 3]);
            float den  = (dch[0] + dch[1]) + (dch[2] + dch[3]);
            float rden = rcpf(den);

            float nch[4];
            nch[0] = fmaf(cmt, v, nb); nch[1] = 0.f; nch[2] = 0.f; nch[3] = 0.f;
            #pragma unroll
            for (int e = 0; e < NL; e++) nch[e & 3] = fmaf(lwe[e], lt[e], nch[e & 3]);
            #pragma unroll
            for (int c = 0; c < NX; c++) nch[(NL + c) & 3] = fmaf(xwe[c], xt[c], nch[(NL + c) & 3]);
            float num = (nch[0] + nch[1]) + (nch[2] + nch[3]);

            v = num * rden;

            // replicated deg-0 source updates (independent FMAs, off chain)
            #pragma unroll
            for (int e = 0; e < NL; e++)
                lv[e] = fmaf(lcmt[e], lv[e], lk[e]) * lr[e];
        }
        sv = nxt;
    }

    if (lane == 0) out[batch] = fmaf(v, ow[0], ob[0]);
}

// classic R4 scan body — fallback
template <int NA>
__device__ void scan_body(
    int lane, int batch,
    const float* __restrict__ gleak, const float* __restrict__ vleak,
    const float* __restrict__ cm,
    const float* __restrict__ ow, const float* __restrict__ ob,
    float* __restrict__ out)
{
    float gl   = gleak[lane];
    float cmt  = cm[lane] * (float)UNF;
    float gv   = gl * vleak[lane];
    float dcst = cmt + gl + EPSV + g_aden0[lane];
    float ncst = g_anum0[lane];

    int src[NA]; float a[NA], b[NA], weh[NA], wdh[NA];
    #pragma unroll
    for (int k = 0; k < NA; k++) {
        src[k] = g_asrc[k * U + lane];
        a[k]   = g_aa[k * U + lane];
        b[k]   = g_ab[k * U + lane];
        weh[k] = g_aweh[k * U + lane];
        wdh[k] = g_awdh[k * U + lane];
    }

    const float2* sp = g_sens + (size_t)batch * TDIM * U + lane;

    verify8(0);
    float2 sv = sp[0];
    float v = 0.f;

    for (int t = 0; t < TDIM; t++) {
        if ((t & 7) == 0 && t + 8 < TDIM) verify8(t + 8);
        int tn = (t + 1 < TDIM) ? (t + 1) : t;
        float2 nxt = sp[(size_t)tn * U];

        float nb = sv.x + ncst + gv;
        float db = sv.y + dcst;

        #pragma unroll
        for (int u = 0; u < UNF; u++) {
            float tk[NA];
            #pragma unroll
            for (int k = 0; k < NA; k++) {
                float vs = __shfl_sync(FULLM, v, src[k]);
                tk[k] = tanhf_a(fmaf(a[k], vs, -b[k]));
            }
            float dch[4];
            dch[0] = db; dch[1] = 0.f; dch[2] = 0.f; dch[3] = 0.f;
            #pragma unroll
            for (int k = 0; k < NA; k++) dch[k & 3] = fmaf(wdh[k], tk[k], dch[k & 3]);
            float den  = (dch[0] + dch[1]) + (dch[2] + dch[3]);
            float rden = rcpf(den);

            float nch[4];
            nch[0] = fmaf(cmt, v, nb); nch[1] = 0.f; nch[2] = 0.f; nch[3] = 0.f;
            #pragma unroll
            for (int k = 0; k < NA; k++) nch[k & 3] = fmaf(weh[k], tk[k], nch[k & 3]);
            float num = (nch[0] + nch[1]) + (nch[2] + nch[3]);

            v = num * rden;
        }
        sv = nxt;
    }

    if (lane == 0) out[batch] = fmaf(v, ow[0], ob[0]);
}

__global__ void __launch_bounds__(256) fused_kernel(
    const float* __restrict__ x,
    const float* __restrict__ d1w, const float* __restrict__ d1b,
    const float* __restrict__ d2w, const float* __restrict__ d2b,
    const float* __restrict__ iw,  const float* __restrict__ ib,
    const float* __restrict__ gleak, const float* __restrict__ vleak,
    const float* __restrict__ cm,
    const float* __restrict__ ow, const float* __restrict__ ob,
    float* __restrict__ out)
{
    extern __shared__ float smem[];
    int tid = threadIdx.x, warp = tid >> 5, lane = tid & 31;

    for (int i = tid; i < 128 * 32; i += 256) {
        int k = i >> 5, j = i & 31;
        smem[j * 132 + k] = d2w[i];
    }
    __syncthreads();

    bool scanBlk = (blockIdx.x < 128);
    if (scanBlk && warp < 2) {
        int batch = blockIdx.x * 2 + warp;
        int nl = g_nloc, nx = g_ncross, ok = g_splitok;
        if (ok && nl <= 4 && nx <= 2)
            scan_split<4, 2>(lane, batch, gleak, vleak, cm, ow, ob, out);
        else if (ok && nl <= 6 && nx <= 4)
            scan_split<6, 4>(lane, batch, gleak, vleak, cm, ow, ob, out);
        else if (ok && nl <= 8 && nx <= 4)
            scan_split<8, 4>(lane, batch, gleak, vleak, cm, ow, ob, out);
        else if (ok && nl <= 8 && nx <= 6)
            scan_split<8, 6>(lane, batch, gleak, vleak, cm, ow, ob, out);
        else {
            int na = g_na;
            if      (na <= 8)  scan_body<8 >(lane, batch, gleak, vleak, cm, ow, ob, out);
            else if (na <= 12) scan_body<12>(lane, batch, gleak, vleak, cm, ow, ob, out);
            else               scan_body<18>(lane, batch, gleak, vleak, cm, ow, ob, out);
        }
    } else if (scanBlk) {
        if (warp == 4 || warp == 5) return;     // keep scan SMSPs clear
        int idx = (warp >= 6) ? (warp - 4) : (warp - 2);
        int sw = blockIdx.x * 4 + idx;
        int nw = 128 * 4 + (gridDim.x - 128) * 8;
        sens_warp(sw, nw, warp, lane, smem, x, d1w, d1b, d2b, iw, ib);
    } else {
        int sw = 128 * 4 + (blockIdx.x - 128) * 8 + warp;
        int nw = 128 * 4 + (gridDim.x - 128) * 8;
        sens_warp(sw, nw, warp, lane, smem, x, d1w, d1b, d2b, iw, ib);
    }
}

// ---------------------------------------------------------------------------
extern "C" void kernel_launch(void* const* d_in, const int* in_sizes, int n_in,
                              void* d_out, int out_size)
{
    const float* x    = (const float*)d_in[0];
    const float* d1w  = (const float*)d_in[1];
    const float* d1b  = (const float*)d_in[2];
    const float* d2w  = (const float*)d_in[3];
    const float* d2b  = (const float*)d_in[4];
    const float* iw   = (const float*)d_in[5];
    const float* ib   = (const float*)d_in[6];
    const float* ow   = (const float*)d_in[7];
    const float* ob   = (const float*)d_in[8];
    const float* gle  = (const float*)d_in[9];
    const float* vle  = (const float*)d_in[10];
    const float* cmv  = (const float*)d_in[11];
    const float* wsyn = (const float*)d_in[12];
    const float* muv  = (const float*)d_in[13];
    const float* sgv  = (const float*)d_in[14];
    const float* erv  = (const float*)d_in[15];
    const float* swv  = (const float*)d_in[16];
    const float* smuv = (const float*)d_in[17];
    const float* ssgv = (const float*)d_in[18];
    const float* serv = (const float*)d_in[19];
    const int*   spm  = (const int*)d_in[20];
    const int*   ssm  = (const int*)d_in[21];

    int nsm = 148;
    cudaDeviceGetAttribute(&nsm, cudaDevAttrMultiProcessorCount, 0);
    int blocks = (nsm > 128) ? nsm : 129;

    const int smemBytes = (32 * 132 + 8 * 1024 + 8 * 256) * sizeof(float);
    cudaFuncSetAttribute(fused_kernel, cudaFuncAttributeMaxDynamicSharedMemorySize, smemBytes);

    setup_kernel<<<1, 1024>>>(spm, wsyn, muv, sgv, erv, ssm, swv, smuv, ssgv, serv);
    fused_kernel<<<blocks, 256, smemBytes>>>(x, d1w, d1b, d2w, d2b, iw, ib,
                                             gle, vle, cmv, ow, ob, (float*)d_out);
}

// round 9
// speedup vs baseline: 2.1541x; 1.5208x over previous
#include <cuda_runtime.h>
#include <cstdint>

#define BDIM 256
#define TDIM 1024
#define U    32
#define UNF  6
#define EPSV 1e-8f
#define AMAX 18
#define SMAX 32
#define FULLM 0xffffffffu
#define NTICK (TDIM * (BDIM / 8))   // 32768 tickets, 8 batch-rows each

// 64 MB scratch: precomputed sensory (num, den) per (b,t,unit)
__device__ float2 g_sens[(size_t)BDIM * TDIM * U];
// per-timestep completion counters (32 tickets per t)
__device__ int g_cnt[TDIM];

// per-column sparse recurrent lists (tanh form), layout [k*U + col]
__device__ int   g_asrc[AMAX * U];
__device__ float g_aa[AMAX * U], g_ab[AMAX * U], g_aweh[AMAX * U], g_awdh[AMAX * U];
__device__ float g_anum0[U], g_aden0[U];
__device__ int   g_na;

// per-column sparse sensory lists (tanh form)
__device__ int   g_ssrc[SMAX * U];
__device__ float g_sa[SMAX * U], g_sb[SMAX * U], g_sweh[SMAX * U], g_swdh[SMAX * U];
__device__ float g_snum0[U], g_sden0[U];
__device__ int   g_ns;

__device__ __forceinline__ float tanhf_a(float x) {
    float r; asm("tanh.approx.f32 %0, %1;" : "=f"(r) : "f"(x)); return r;
}
__device__ __forceinline__ float rcpf(float x) {
    float r; asm("rcp.approx.ftz.f32 %0, %1;" : "=f"(r) : "f"(x)); return r;
}
__device__ __forceinline__ int ld_acq(const int* p) {
    int v; asm volatile("ld.acquire.gpu.global.b32 %0, [%1];" : "=r"(v) : "l"(p)); return v;
}

// ---------------------------------------------------------------------------
// Setup: build lists (tanh form) + zero the per-t counters.
// sigmoid(s(v-mu)) = 0.5 + 0.5*tanh(a*v - b), a = 0.5*s, b = 0.5*s*mu.
// ---------------------------------------------------------------------------
__global__ void __launch_bounds__(1024) setup_kernel(
    const int* __restrict__ spm, const float* __restrict__ wsyn,
    const float* __restrict__ mu, const float* __restrict__ sg,
    const float* __restrict__ er,
    const int* __restrict__ ssm, const float* __restrict__ sw,
    const float* __restrict__ smu, const float* __restrict__ ssg,
    const float* __restrict__ ser)
{
    __shared__ int   s_m[1024]; __shared__ float s_w[1024], s_mu[1024], s_sg[1024], s_er[1024];
    __shared__ int   t_m[1024]; __shared__ float t_w[1024], t_mu[1024], t_sg[1024], t_er[1024];
    int tid = threadIdx.x;
    g_cnt[tid] = 0;                            // reset readiness counters (every launch)
    s_m[tid] = spm[tid]; s_w[tid] = wsyn[tid]; s_mu[tid] = mu[tid];
    s_sg[tid] = sg[tid]; s_er[tid] = er[tid];
    t_m[tid] = ssm[tid]; t_w[tid] = sw[tid];  t_mu[tid] = smu[tid];
    t_sg[tid] = ssg[tid]; t_er[tid] = ser[tid];
    __syncthreads();

    if (tid < 32) {                       // recurrent lists, column j = tid
        int j = tid, cnt = 0;
        float n0 = 0.f, d0 = 0.f;
        for (int i = 0; i < U; i++) {
            int idx = i * U + j;
            if (s_m[idx] != 0 && cnt < AMAX) {
                float a = 0.5f * s_sg[idx];
                float weh = 0.5f * s_w[idx] * s_er[idx];
                float wdh = 0.5f * s_w[idx];
                g_asrc[cnt * U + j] = i;
                g_aa[cnt * U + j]   = a;
                g_ab[cnt * U + j]   = a * s_mu[idx];
                g_aweh[cnt * U + j] = weh;
                g_awdh[cnt * U + j] = wdh;
                n0 += weh; d0 += wdh;
                cnt++;
            }
        }
        for (int k = cnt; k < AMAX; k++) {
            g_asrc[k * U + j] = 0;
            g_aa[k * U + j] = 0.f; g_ab[k * U + j] = 0.f;
            g_aweh[k * U + j] = 0.f; g_awdh[k * U + j] = 0.f;
        }
        g_anum0[j] = n0; g_aden0[j] = d0;
        int m = cnt;
        #pragma unroll
        for (int o = 16; o > 0; o >>= 1) m = max(m, __shfl_xor_sync(FULLM, m, o));
        if (j == 0) g_na = m;
    } else if (tid < 64) {                // sensory lists, column j = tid-32
        int j = tid - 32, cnt = 0;
        float n0 = 0.f, d0 = 0.f;
        for (int i = 0; i < U; i++) {
            int idx = i * U + j;
            if (t_m[idx] != 0 && cnt < SMAX) {
                float a = 0.5f * t_sg[idx];
                float weh = 0.5f * t_w[idx] * t_er[idx];
                float wdh = 0.5f * t_w[idx];
                g_ssrc[cnt * U + j] = i;
                g_sa[cnt * U + j]   = a;
                g_sb[cnt * U + j]   = a * t_mu[idx];
                g_sweh[cnt * U + j] = weh;
                g_swdh[cnt * U + j] = wdh;
                n0 += weh; d0 += wdh;
                cnt++;
            }
        }
        for (int k = cnt; k < SMAX; k++) {
            g_ssrc[k * U + j] = 0;
            g_sa[k * U + j] = 0.f; g_sb[k * U + j] = 0.f;
            g_sweh[k * U + j] = 0.f; g_swdh[k * U + j] = 0.f;
        }
        g_snum0[j] = n0; g_sden0[j] = d0;
        int m = cnt;
        #pragma unroll
        for (int o = 16; o > 0; o >>= 1) m = max(m, __shfl_xor_sync(FULLM, m, o));
        if (j == 0) g_ns = m;
    }
}

// ---------------------------------------------------------------------------
// Fused producer/consumer kernel.
// Blocks 0..127: warps 0,1 = scan (batches 2*bid, 2*bid+1), warps 2,3,6,7 = sens,
//                warps 4,5 exit (keep scan SMSPs free of sens MUFU traffic).
// Blocks >=128: all 8 warps = sens.
// ---------------------------------------------------------------------------

// sens worker: processes tickets (t, 8-batch group) in t-major static partition.
__device__ void sens_warp(
    int sw, int nw, int warp, int lane, float* smem,
    const float* __restrict__ x,
    const float* __restrict__ d1w, const float* __restrict__ d1b,
    const float* __restrict__ d2b,
    const float* __restrict__ iw,  const float* __restrict__ ib)
{
    float* sh_w2t = smem;                       // [32][132]
    float* sh_h1  = smem + 32 * 132 + warp * 1024;   // [8][128] per warp
    float* sh_in  = smem + 32 * 132 + 8 * 1024 + warp * 256; // [8][32] per warp

    // hoisted per-warp constants
    float wa[4], wb[4], bb[4];
    #pragma unroll
    for (int c = 0; c < 4; c++) {
        int k = c * 32 + lane;
        wa[c] = d1w[k]; wb[c] = d1w[128 + k]; bb[c] = d1b[k];
    }
    float dbl = d2b[lane], iwl = iw[lane], ibl = ib[lane];
    float n0 = g_snum0[lane], d0 = g_sden0[lane];
    int ns = g_ns;

    for (int q = sw; q < NTICK; q += nw) {
        int t  = q >> 5;
        int b0 = (q & 31) << 3;

        float2 xv = make_float2(0.f, 0.f);
        if (lane < 8) xv = ((const float2*)x)[(size_t)(b0 + lane) * TDIM + t];

        #pragma unroll
        for (int r = 0; r < 8; r++) {
            float x0 = __shfl_sync(FULLM, xv.x, r);
            float x1 = __shfl_sync(FULLM, xv.y, r);
            #pragma unroll
            for (int c = 0; c < 4; c++) {
                int k = c * 32 + lane;
                sh_h1[r * 128 + k] = fmaxf(fmaf(x0, wa[c], fmaf(x1, wb[c], bb[c])), 0.f);
            }
        }
        __syncwarp();

        float acc[8];
        #pragma unroll
        for (int r = 0; r < 8; r++) acc[r] = dbl;
        #pragma unroll 8
        for (int kq = 0; kq < 32; kq++) {
            float4 w4 = *(const float4*)&sh_w2t[lane * 132 + kq * 4];
            #pragma unroll
            for (int r = 0; r < 8; r++) {
                float4 h4 = *(const float4*)&sh_h1[r * 128 + kq * 4];
                acc[r] = fmaf(h4.x, w4.x, acc[r]);
                acc[r] = fmaf(h4.y, w4.y, acc[r]);
                acc[r] = fmaf(h4.z, w4.z, acc[r]);
                acc[r] = fmaf(h4.w, w4.w, acc[r]);
            }
        }
        #pragma unroll
        for (int r = 0; r < 8; r++) sh_in[r * 32 + lane] = fmaf(acc[r], iwl, ibl);
        __syncwarp();

        float num[8], den[8];
        #pragma unroll
        for (int r = 0; r < 8; r++) { num[r] = n0; den[r] = d0; }
        for (int k = 0; k < ns; k++) {
            int   src = g_ssrc[k * U + lane];
            float a   = g_sa[k * U + lane];
            float b   = g_sb[k * U + lane];
            float weh = g_sweh[k * U + lane];
            float wdh = g_swdh[k * U + lane];
            #pragma unroll
            for (int r = 0; r < 8; r++) {
                float tk = tanhf_a(fmaf(a, sh_in[r * 32 + src], -b));
                num[r] = fmaf(weh, tk, num[r]);
                den[r] = fmaf(wdh, tk, den[r]);
            }
        }
        #pragma unroll
        for (int r = 0; r < 8; r++)
            g_sens[((size_t)(b0 + r) * TDIM + t) * U + lane] = make_float2(num[r], den[r]);

        __threadfence();                        // release: data before counter
        if (lane == 0) atomicAdd(&g_cnt[t], 1);
        __syncwarp();
    }
}

// verify 8 timesteps [base, base+8) are fully produced (32 tickets each)
__device__ __forceinline__ void verify8(int base) {
    for (;;) {
        int ok = 1;
        #pragma unroll
        for (int i = 0; i < 8; i++)
            ok &= (ld_acq(&g_cnt[base + i]) == 32);
        if (ok) return;
        __nanosleep(200);
    }
}

template <int NA>
__device__ void scan_body(
    int lane, int batch,
    const float* __restrict__ gleak, const float* __restrict__ vleak,
    const float* __restrict__ cm,
    const float* __restrict__ ow, const float* __restrict__ ob,
    float* __restrict__ out)
{
    float gl   = gleak[lane];
    float cmt  = cm[lane] * (float)UNF;
    float gv   = gl * vleak[lane];
    float dcst = cmt + gl + EPSV + g_aden0[lane];
    float ncst = g_anum0[lane];

    int src[NA]; float a[NA], b[NA], weh[NA], wdh[NA];
    #pragma unroll
    for (int k = 0; k < NA; k++) {
        src[k] = g_asrc[k * U + lane];
        a[k]   = g_aa[k * U + lane];
        b[k]   = g_ab[k * U + lane];
        weh[k] = g_aweh[k * U + lane];
        wdh[k] = g_awdh[k * U + lane];
    }

    const float2* sp = g_sens + (size_t)batch * TDIM * U + lane;

    verify8(0);
    float2 sv = sp[0];
    float v = 0.f;

    for (int t = 0; t < TDIM; t++) {
        if ((t & 7) == 0 && t + 8 < TDIM) verify8(t + 8);  // stay 8 steps ahead
        int tn = (t + 1 < TDIM) ? (t + 1) : t;
        float2 nxt = sp[(size_t)tn * U];

        float nb = sv.x + ncst;
        float db = sv.y + dcst;

        #pragma unroll
        for (int u = 0; u < UNF; u++) {
            float p = fmaf(cmt, v, gv);
            float tk[NA];
            #pragma unroll
            for (int k = 0; k < NA; k++) {
                float vs = __shfl_sync(FULLM, v, src[k]);
                tk[k] = tanhf_a(fmaf(a[k], vs, -b[k]));
            }
            // 4-way interleaved fma chains (low register pressure, depth ~NA)
            float nch[4], dch[4];
            nch[0] = p + nb; nch[1] = 0.f; nch[2] = 0.f; nch[3] = 0.f;
            dch[0] = db;     dch[1] = 0.f; dch[2] = 0.f; dch[3] = 0.f;
            #pragma unroll
            for (int k = 0; k < NA; k++) {
                nch[k & 3] = fmaf(weh[k], tk[k], nch[k & 3]);
                dch[k & 3] = fmaf(wdh[k], tk[k], dch[k & 3]);
            }
            float num = (nch[0] + nch[1]) + (nch[2] + nch[3]);
            float den = (dch[0] + dch[1]) + (dch[2] + dch[3]);
            v = num * rcpf(den);
        }
        sv = nxt;
    }

    if (lane == 0) out[batch] = fmaf(v, ow[0], ob[0]);
}

__global__ void __launch_bounds__(256) fused_kernel(
    const float* __restrict__ x,
    const float* __restrict__ d1w, const float* __restrict__ d1b,
    const float* __restrict__ d2w, const float* __restrict__ d2b,
    const float* __restrict__ iw,  const float* __restrict__ ib,
    const float* __restrict__ gleak, const float* __restrict__ vleak,
    const float* __restrict__ cm,
    const float* __restrict__ ow, const float* __restrict__ ob,
    float* __restrict__ out)
{
    extern __shared__ float smem[];
    int tid = threadIdx.x, warp = tid >> 5, lane = tid & 31;

    // stage d2_w transposed [j][k] padded to 132 (conflict-free float4 column reads)
    for (int i = tid; i < 128 * 32; i += 256) {
        int k = i >> 5, j = i & 31;
        smem[j * 132 + k] = d2w[i];
    }
    __syncthreads();

    bool scanBlk = (blockIdx.x < 128);
    if (scanBlk && warp < 2) {
        int batch = blockIdx.x * 2 + warp;
        int na = g_na;
        if      (na <= 4)  scan_body<4 >(lane, batch, gleak, vleak, cm, ow, ob, out);
        else if (na <= 6)  scan_body<6 >(lane, batch, gleak, vleak, cm, ow, ob, out);
        else if (na <= 8)  scan_body<8 >(lane, batch, gleak, vleak, cm, ow, ob, out);
        else if (na <= 10) scan_body<10>(lane, batch, gleak, vleak, cm, ow, ob, out);
        else if (na <= 12) scan_body<12>(lane, batch, gleak, vleak, cm, ow, ob, out);
        else               scan_body<18>(lane, batch, gleak, vleak, cm, ow, ob, out);
    } else if (scanBlk) {
        if (warp == 4 || warp == 5) return;     // keep SMSP 0/1 for scan warps
        int idx = (warp >= 6) ? (warp - 4) : (warp - 2);  // {2,3,6,7} -> {0,1,2,3}
        int sw = blockIdx.x * 4 + idx;
        int nw = 128 * 4 + (gridDim.x - 128) * 8;
        sens_warp(sw, nw, warp, lane, smem, x, d1w, d1b, d2b, iw, ib);
    } else {
        int sw = 128 * 4 + (blockIdx.x - 128) * 8 + warp;
        int nw = 128 * 4 + (gridDim.x - 128) * 8;
        sens_warp(sw, nw, warp, lane, smem, x, d1w, d1b, d2b, iw, ib);
    }
}

// ---------------------------------------------------------------------------
extern "C" void kernel_launch(void* const* d_in, const int* in_sizes, int n_in,
                              void* d_out, int out_size)
{
    const float* x    = (const float*)d_in[0];
    const float* d1w  = (const float*)d_in[1];
    const float* d1b  = (const float*)d_in[2];
    const float* d2w  = (const float*)d_in[3];
    const float* d2b  = (const float*)d_in[4];
    const float* iw   = (const float*)d_in[5];
    const float* ib   = (const float*)d_in[6];
    const float* ow   = (const float*)d_in[7];
    const float* ob   = (const float*)d_in[8];
    const float* gle  = (const float*)d_in[9];
    const float* vle  = (const float*)d_in[10];
    const float* cmv  = (const float*)d_in[11];
    const float* wsyn = (const float*)d_in[12];
    const float* muv  = (const float*)d_in[13];
    const float* sgv  = (const float*)d_in[14];
    const float* erv  = (const float*)d_in[15];
    const float* swv  = (const float*)d_in[16];
    const float* smuv = (const float*)d_in[17];
    const float* ssgv = (const float*)d_in[18];
    const float* serv = (const float*)d_in[19];
    const int*   spm  = (const int*)d_in[20];
    const int*   ssm  = (const int*)d_in[21];

    int nsm = 148;
    cudaDeviceGetAttribute(&nsm, cudaDevAttrMultiProcessorCount, 0);
    int blocks = (nsm > 128) ? nsm : 129;   // >=129 so at least 1 all-sens block

    const int smemBytes = (32 * 132 + 8 * 1024 + 8 * 256) * sizeof(float); // ~57.5 KB
    static_assert((32 * 132 + 8 * 1024 + 8 * 256) * sizeof(float) < 100 * 1024, "");
    cudaFuncSetAttribute(fused_kernel, cudaFuncAttributeMaxDynamicSharedMemorySize, smemBytes);

    setup_kernel<<<1, 1024>>>(spm, wsyn, muv, sgv, erv, ssm, swv, smuv, ssgv, serv);
    fused_kernel<<<blocks, 256, smemBytes>>>(x, d1w, d1b, d2w, d2b, iw, ib,
                                             gle, vle, cmv, ow, ob, (float*)d_out);
}